// round 15
// baseline (speedup 1.0000x reference)
#include <cuda_runtime.h>

#define N_NODES  100000
#define N_EDGES  1600000
#define HID      128
#define IN_F     10
#define OUT_F    101
#define N_GRAPHS 64
#define NTHR     256
#define NSC      ((N_NODES + NTHR - 1) / NTHR)   // 391 scan blocks

// ---------------- device state (single-launch lifetime) ------------------------
__device__ __align__(16) float d_h0[(size_t)N_NODES * HID];
__device__ __align__(16) float d_h1[(size_t)N_NODES * HID];
__device__ int   d_deg[N_NODES];
__device__ float d_dis[N_NODES];
__device__ int   d_rowptr[N_NODES];
__device__ int   d_cursor[N_NODES];
__device__ int   d_bsum[NSC];
__device__ int   d_csr_src[N_EDGES];
__device__ float d_gsum[N_GRAPHS * HID];
__device__ int   d_gcnt[N_GRAPHS];
__device__ int   d_ei64, d_b64;
__device__ int          g_arrive;     // arrival ticket (monotonic)
__device__ volatile int g_release;    // generation release word (monotonic)

__device__ __forceinline__ int ld_idx(const int* __restrict__ p, int i, int is64) {
    return is64 ? __ldg(p + 2 * (size_t)i) : __ldg(p + i);
}

// packed fp32x2 FMA (full-rate fp32 on sm_103a; plain FFMA is half-rate)
#define FFMA2(acc, a, b) \
    asm("fma.rn.f32x2 %0, %1, %2, %0;" : "+l"(acc) : "l"(a), "l"(b))
#define PACKVV(out, v) \
    asm("mov.b64 %0, {%1, %1};" : "=l"(out) : "r"(__float_as_uint(v)))

// L2-only float4 load (bypass L1 for streamed, non-reused rows)
__device__ __forceinline__ float4 ldcg4(const float4* p) { return __ldcg(p); }

// Grid barrier v2: atomic ARRIVE only; waiters poll a plain release word
// (single-address atomic polling serializes in L2 and cost ~5-10us/barrier).
__device__ __forceinline__ void gbar() {
    __syncthreads();
    if (threadIdx.x == 0) {
        __threadfence();                          // publish this block's writes
        int g   = gridDim.x;
        int t   = atomicAdd(&g_arrive, 1);
        int gen = t / g;
        if (t % g == g - 1) {
            g_release = gen + 1;                  // last arriver broadcasts
        } else {
            while (g_release <= gen) __nanosleep(64);
        }
        __threadfence();                          // acquire side
    }
    __syncthreads();
}

// ---------------- XFORM: d_h0 = d_h1 @ W (warp per 4 rows, f32x2 packed) ------
__device__ __forceinline__ void xform128(const float* __restrict__ W,
                                         int wid, int nw, int lane) {
    for (int q = wid; q < N_NODES / 4; q += nw) {
        const float* r = d_h1 + (size_t)(4 * q) * HID;
        unsigned long long a01[4] = {0ull, 0ull, 0ull, 0ull};
        unsigned long long a23[4] = {0ull, 0ull, 0ull, 0ull};
        #pragma unroll 2
        for (int k4 = 0; k4 < HID; k4 += 4) {
            float4 xr[4];
            #pragma unroll
            for (int t = 0; t < 4; t++)
                xr[t] = ldcg4((const float4*)(r + t * HID + k4));   // streamed: L2 only
            #pragma unroll
            for (int kk = 0; kk < 4; kk++) {
                double2 wp = __ldg((const double2*)(W + (size_t)(k4 + kk) * HID) + lane);
                unsigned long long w01 = (unsigned long long)__double_as_longlong(wp.x);
                unsigned long long w23 = (unsigned long long)__double_as_longlong(wp.y);
                #pragma unroll
                for (int t = 0; t < 4; t++) {
                    float v = (kk == 0) ? xr[t].x : (kk == 1) ? xr[t].y
                             : (kk == 2) ? xr[t].z : xr[t].w;
                    unsigned long long vv;
                    PACKVV(vv, v);
                    FFMA2(a01[t], w01, vv);
                    FFMA2(a23[t], w23, vv);
                }
            }
        }
        #pragma unroll
        for (int t = 0; t < 4; t++) {
            double2 st;
            st.x = __longlong_as_double((long long)a01[t]);
            st.y = __longlong_as_double((long long)a23[t]);
            ((double2*)(d_h0 + (size_t)(4 * q + t) * HID))[lane] = st;
        }
    }
}

// ---------------- GATHER: d_h1 = A_norm*d_h0 + bias (double-buffered) ---------
__device__ __forceinline__ void gather128(const float* __restrict__ bias, int relu,
                                          int wid, int nw, int lane) {
    const float4* h0v = (const float4*)d_h0;
    for (int node = wid; node < N_NODES; node += nw) {
        float dv = d_dis[node];
        float4 h = ldcg4(h0v + (size_t)node * 32 + lane);
        float sw = dv * dv;
        float4 acc;
        acc.x = sw * h.x; acc.y = sw * h.y; acc.z = sw * h.z; acc.w = sw * h.w;
        int st  = d_rowptr[node];
        int cnt = d_deg[node] - 1;
        float4 v = make_float4(0.f, 0.f, 0.f, 0.f);
        float  w = 0.f;
        if (cnt > 0) {
            int s0 = __ldg(d_csr_src + st);
            v = ldcg4(h0v + (size_t)s0 * 32 + lane);
            w = __ldg(&d_dis[s0]) * dv;
        }
        for (int j = 0; j < cnt; j++) {
            float4 vn; float wn;
            if (j + 1 < cnt) {                       // prefetch next row+weight
                int sn = __ldg(d_csr_src + st + j + 1);
                vn = ldcg4(h0v + (size_t)sn * 32 + lane);
                wn = __ldg(&d_dis[sn]) * dv;
            }
            acc.x += w * v.x; acc.y += w * v.y;
            acc.z += w * v.z; acc.w += w * v.w;
            if (j + 1 < cnt) { v = vn; w = wn; }
        }
        float4 b = __ldg((const float4*)bias + lane);
        acc.x += b.x; acc.y += b.y; acc.z += b.z; acc.w += b.w;
        if (relu) {
            acc.x = fmaxf(acc.x, 0.f); acc.y = fmaxf(acc.y, 0.f);
            acc.z = fmaxf(acc.z, 0.f); acc.w = fmaxf(acc.w, 0.f);
        }
        ((float4*)(d_h1 + (size_t)node * HID))[lane] = acc;
    }
}

__global__ void __launch_bounds__(NTHR, 4)
k_uber(const float* __restrict__ x, const int* __restrict__ ei,
       const int* __restrict__ batch,
       const float* __restrict__ W1, const float* __restrict__ b1,
       const float* __restrict__ W2, const float* __restrict__ b2,
       const float* __restrict__ W3, const float* __restrict__ b3,
       const float* __restrict__ Wl, const float* __restrict__ bl,
       float* __restrict__ out) {
    const int NT   = gridDim.x * blockDim.x;
    const int gt   = blockIdx.x * blockDim.x + threadIdx.x;
    const int lane = threadIdx.x & 31;
    const int wid  = gt >> 5;
    const int nw   = NT >> 5;
    __shared__ int sh[512];

    // ---- P0: init + dtype detection ----
    for (int i = gt; i < N_NODES; i += NT) d_deg[i] = 1;        // self-loop
    for (int i = gt; i < N_GRAPHS * HID; i += NT) d_gsum[i] = 0.f;
    for (int i = gt; i < N_GRAPHS; i += NT) d_gcnt[i] = 0;
    if (blockIdx.x == 0) {
        __shared__ int s_ei, s_b;
        if (threadIdx.x == 0) { s_ei = 1; s_b = 1; }
        __syncthreads();
        for (int k = 0; k < 8; k++) {
            int t = threadIdx.x * 8 + k;
            if (__ldg(ei + ((t * (2 * N_EDGES / 2048)) | 1)) != 0) s_ei = 0;
            if (__ldg(batch + ((t * (N_NODES / 2048)) | 1)) != 0) s_b = 0;
        }
        __syncthreads();
        if (threadIdx.x == 0) { d_ei64 = s_ei; d_b64 = s_b; }
    }
    gbar();
    const int ef = d_ei64;
    const int bf = d_b64;

    // ---- P1: degree histogram ----
    for (int e = gt; e < N_EDGES; e += NT)
        atomicAdd(&d_deg[ld_idx(ei, N_EDGES + e, ef)], 1);
    gbar();

    // ---- P2: dis = rsqrt(deg) + scan phase A ----
    for (int i = gt; i < N_NODES; i += NT)
        d_dis[i] = rsqrtf((float)d_deg[i]);
    if (blockIdx.x < NSC) {
        int i = blockIdx.x * NTHR + threadIdx.x;
        int c = (i < N_NODES) ? (d_deg[i] - 1) : 0;
        sh[threadIdx.x] = c;
        __syncthreads();
        #pragma unroll
        for (int off = 1; off < NTHR; off <<= 1) {
            int t = (threadIdx.x >= off) ? sh[threadIdx.x - off] : 0;
            __syncthreads();
            sh[threadIdx.x] += t;
            __syncthreads();
        }
        if (i < N_NODES) d_rowptr[i] = sh[threadIdx.x] - c;
        if (threadIdx.x == NTHR - 1) d_bsum[blockIdx.x] = sh[NTHR - 1];
    }
    gbar();

    // ---- P3: scan phase B ----
    if (blockIdx.x == 0) {
        for (int t = threadIdx.x; t < NSC; t += NTHR) sh[t] = d_bsum[t];
        __syncthreads();
        if (threadIdx.x == 0) {
            int run = 0;
            for (int b = 0; b < NSC; b++) { int t = sh[b]; sh[b] = run; run += t; }
        }
        __syncthreads();
        for (int t = threadIdx.x; t < NSC; t += NTHR) d_bsum[t] = sh[t];
    }
    gbar();

    // ---- P4: scan phase C ----
    for (int i = gt; i < N_NODES; i += NT) {
        int v = d_rowptr[i] + d_bsum[i / NTHR];
        d_rowptr[i] = v;
        d_cursor[i] = v;
    }
    gbar();

    // ---- P5: CSR fill ----
    for (int e = gt; e < N_EDGES; e += NT) {
        int s = ld_idx(ei, e, ef);
        int d = ld_idx(ei, N_EDGES + e, ef);
        d_csr_src[atomicAdd(&d_cursor[d], 1)] = s;
    }
    gbar();

    // ---- P6: fused xa-gather + layer-1 transform (warp per node) ----
    for (int node = wid; node < N_NODES; node += nw) {
        float dv = d_dis[node];
        float a = 0.f;
        if (lane < IN_F)
            a = dv * dv * __ldg(x + (size_t)node * IN_F + lane);
        int st = d_rowptr[node], cnt = d_deg[node] - 1;
        for (int j = 0; j < cnt; j++) {
            int s = __ldg(d_csr_src + st + j);
            float w = __ldg(&d_dis[s]) * dv;
            if (lane < IN_F)
                a += w * __ldg(x + (size_t)s * IN_F + lane);
        }
        float4 acc = __ldg((const float4*)b1 + lane);
        #pragma unroll
        for (int k = 0; k < IN_F; k++) {
            float v = __shfl_sync(0xffffffffu, a, k);
            float4 w = __ldg((const float4*)W1 + k * 32 + lane);
            acc.x += v * w.x; acc.y += v * w.y;
            acc.z += v * w.z; acc.w += v * w.w;
        }
        acc.x = fmaxf(acc.x, 0.f); acc.y = fmaxf(acc.y, 0.f);
        acc.z = fmaxf(acc.z, 0.f); acc.w = fmaxf(acc.w, 0.f);
        ((float4*)(d_h1 + (size_t)node * HID))[lane] = acc;
    }
    gbar();

    // ---- P7-P8: layer 2 ----
    xform128(W2, wid, nw, lane); gbar();
    gather128(b2, 1, wid, nw, lane); gbar();
    // ---- P9-P10: layer 3 (no relu) ----
    xform128(W3, wid, nw, lane); gbar();
    gather128(b3, 0, wid, nw, lane); gbar();

    // ---- P11: segmented mean-pool (batch sorted => few flushes) ----
    {
        int per = (N_NODES + nw - 1) / nw;
        int n0 = wid * per;
        int n1 = (n0 + per < N_NODES) ? n0 + per : N_NODES;
        if (n0 < n1) {
            float4 acc = make_float4(0.f, 0.f, 0.f, 0.f);
            int cnt = 0;
            int curg = ld_idx(batch, n0, bf);
            for (int n = n0; n < n1; n++) {
                int g = ld_idx(batch, n, bf);
                if (g != curg) {
                    float* base = d_gsum + curg * HID + lane * 4;
                    atomicAdd(base + 0, acc.x); atomicAdd(base + 1, acc.y);
                    atomicAdd(base + 2, acc.z); atomicAdd(base + 3, acc.w);
                    if (lane == 0) atomicAdd(&d_gcnt[curg], cnt);
                    acc = make_float4(0.f, 0.f, 0.f, 0.f);
                    cnt = 0;
                    curg = g;
                }
                float4 v = ((const float4*)(d_h1 + (size_t)n * HID))[lane];
                acc.x += v.x; acc.y += v.y; acc.z += v.z; acc.w += v.w;
                cnt++;
            }
            float* base = d_gsum + curg * HID + lane * 4;
            atomicAdd(base + 0, acc.x); atomicAdd(base + 1, acc.y);
            atomicAdd(base + 2, acc.z); atomicAdd(base + 3, acc.w);
            if (lane == 0) atomicAdd(&d_gcnt[curg], cnt);
        }
    }
    gbar();

    // ---- P12: head ----
    for (int i = gt; i < N_GRAPHS * OUT_F; i += NT) {
        int g = i / OUT_F, c = i - g * OUT_F;
        float inv = 1.f / (float)max(d_gcnt[g], 1);
        float acc = __ldg(bl + c);
        #pragma unroll 8
        for (int k = 0; k < HID; k++)
            acc += (d_gsum[g * HID + k] * inv) * __ldg(Wl + k * OUT_F + c);
        out[i] = acc;
    }
}

// ---------------- launch ---------------------------------------------------------
extern "C" void kernel_launch(void* const* d_in, const int* in_sizes, int n_in,
                              void* d_out, int out_size) {
    const float *x = 0, *W1 = 0, *W2 = 0, *W3 = 0, *Wl = 0, *bl = 0;
    const float *bias[3] = {0, 0, 0};
    const int *ei = 0, *batch = 0;
    int nbias = 0, nW = 0;
    for (int i = 0; i < n_in; i++) {
        int sz = in_sizes[i];
        const void* p = d_in[i];
        switch (sz) {
            case N_NODES * IN_F:   x     = (const float*)p;  break;
            case 2 * N_EDGES:      ei    = (const int*)p;    break;
            case N_NODES:          batch = (const int*)p;    break;
            case IN_F * HID:       W1    = (const float*)p;  break;
            case HID * HID:        if (nW == 0) W2 = (const float*)p; else W3 = (const float*)p; nW++; break;
            case HID:              if (nbias < 3) bias[nbias++] = (const float*)p; break;
            case HID * OUT_F:      Wl    = (const float*)p;  break;
            case OUT_F:            bl    = (const float*)p;  break;
            default: break;
        }
    }

    int sm = 148, mb = 1;
    cudaDeviceGetAttribute(&sm, cudaDevAttrMultiProcessorCount, 0);
    cudaOccupancyMaxActiveBlocksPerMultiprocessor(&mb, k_uber, NTHR, 0);
    if (mb < 1) mb = 1;
    if (mb > 4) mb = 4;
    int grid = sm * mb;

    k_uber<<<grid, NTHR>>>(x, ei, batch,
                           W1, bias[0], W2, bias[1], W3, bias[2],
                           Wl, bl, (float*)d_out);
}

// round 16
// speedup vs baseline: 1.1335x; 1.1335x over previous
#include <cuda_runtime.h>

#define N_NODES  100000
#define N_EDGES  1600000
#define HID      128
#define IN_F     10
#define OUT_F    101
#define N_GRAPHS 64
#define NTHR     256
#define NSC      ((N_NODES + NTHR - 1) / NTHR)   // 391 scan blocks

// ---------------- device state (single-launch lifetime) ------------------------
__device__ __align__(16) float d_h0[(size_t)N_NODES * HID];
__device__ __align__(16) float d_h1[(size_t)N_NODES * HID];
__device__ int   d_deg[N_NODES];
__device__ float d_dis[N_NODES];
__device__ int   d_rowptr[N_NODES];
__device__ int   d_cursor[N_NODES];
__device__ int   d_bsum[NSC];
__device__ int   d_csr_src[N_EDGES];
__device__ float d_gsum[N_GRAPHS * HID];
__device__ int   d_gcnt[N_GRAPHS];
__device__ int   d_ei64, d_b64;
__device__ int          g_arrive;     // arrival ticket (monotonic)
__device__ volatile int g_release;    // generation release word (monotonic)

__device__ __forceinline__ int ld_idx(const int* __restrict__ p, int i, int is64) {
    return is64 ? __ldg(p + 2 * (size_t)i) : __ldg(p + i);
}

// packed fp32x2 FMA (full-rate fp32 on sm_103a; plain FFMA is half-rate)
#define FFMA2(acc, a, b) \
    asm("fma.rn.f32x2 %0, %1, %2, %0;" : "+l"(acc) : "l"(a), "l"(b))
#define PACKVV(out, v) \
    asm("mov.b64 %0, {%1, %1};" : "=l"(out) : "r"(__float_as_uint(v)))

// Grid barrier v2: atomic ARRIVE only; waiters poll a plain release word.
// v1's atomic polling serialized on the L2 atomic ALU and starved the phase
// stragglers (CSR-cursor / pool atomics) -> stretched every phase tail.
__device__ __forceinline__ void gbar() {
    __syncthreads();
    if (threadIdx.x == 0) {
        __threadfence();                          // publish this block's writes
        int g   = gridDim.x;
        int t   = atomicAdd(&g_arrive, 1);
        int gen = t / g;
        if (t % g == g - 1) {
            g_release = gen + 1;                  // last arriver broadcasts
        } else {
            while (g_release <= gen) __nanosleep(64);
        }
        __threadfence();                          // acquire side
    }
    __syncthreads();
}

// ---------------- XFORM: d_h0 = d_h1 @ W (warp per 4 rows, f32x2 packed) ------
// Row loads are PLAIN (L1-cached): sequential 16B slices of the same 128B lines
// get intra-row spatial reuse from L1 (the R15 __ldcg variant broke this).
__device__ __forceinline__ void xform128(const float* __restrict__ W,
                                         int wid, int nw, int lane) {
    for (int q = wid; q < N_NODES / 4; q += nw) {
        const float* r = d_h1 + (size_t)(4 * q) * HID;
        unsigned long long a01[4] = {0ull, 0ull, 0ull, 0ull};
        unsigned long long a23[4] = {0ull, 0ull, 0ull, 0ull};
        #pragma unroll 2
        for (int k4 = 0; k4 < HID; k4 += 4) {
            float4 xr[4];
            #pragma unroll
            for (int t = 0; t < 4; t++)
                xr[t] = *(const float4*)(r + t * HID + k4);
            #pragma unroll
            for (int kk = 0; kk < 4; kk++) {
                double2 wp = __ldg((const double2*)(W + (size_t)(k4 + kk) * HID) + lane);
                unsigned long long w01 = (unsigned long long)__double_as_longlong(wp.x);
                unsigned long long w23 = (unsigned long long)__double_as_longlong(wp.y);
                #pragma unroll
                for (int t = 0; t < 4; t++) {
                    float v = (kk == 0) ? xr[t].x : (kk == 1) ? xr[t].y
                             : (kk == 2) ? xr[t].z : xr[t].w;
                    unsigned long long vv;
                    PACKVV(vv, v);
                    FFMA2(a01[t], w01, vv);
                    FFMA2(a23[t], w23, vv);
                }
            }
        }
        #pragma unroll
        for (int t = 0; t < 4; t++) {
            double2 st;
            st.x = __longlong_as_double((long long)a01[t]);
            st.y = __longlong_as_double((long long)a23[t]);
            ((double2*)(d_h0 + (size_t)(4 * q + t) * HID))[lane] = st;
        }
    }
}

// ---------------- GATHER: d_h1 = A_norm*d_h0 + bias (R14 index-prefetch form) --
__device__ __forceinline__ void gather128(const float* __restrict__ bias, int relu,
                                          int wid, int nw, int lane) {
    for (int node = wid; node < N_NODES; node += nw) {
        float dv = d_dis[node];
        float4 h = ((const float4*)(d_h0 + (size_t)node * HID))[lane];
        float sw = dv * dv;
        float4 acc;
        acc.x = sw * h.x; acc.y = sw * h.y; acc.z = sw * h.z; acc.w = sw * h.w;
        int st = d_rowptr[node];
        int cnt = d_deg[node] - 1;
        int sn = (cnt > 0) ? __ldg(d_csr_src + st) : 0;
        for (int j = 0; j < cnt; j++) {
            int s = sn;
            if (j + 1 < cnt) sn = __ldg(d_csr_src + st + j + 1);
            float w = __ldg(&d_dis[s]) * dv;
            float4 v = ((const float4*)(d_h0 + (size_t)s * HID))[lane];
            acc.x += w * v.x; acc.y += w * v.y;
            acc.z += w * v.z; acc.w += w * v.w;
        }
        float4 b = __ldg((const float4*)bias + lane);
        acc.x += b.x; acc.y += b.y; acc.z += b.z; acc.w += b.w;
        if (relu) {
            acc.x = fmaxf(acc.x, 0.f); acc.y = fmaxf(acc.y, 0.f);
            acc.z = fmaxf(acc.z, 0.f); acc.w = fmaxf(acc.w, 0.f);
        }
        ((float4*)(d_h1 + (size_t)node * HID))[lane] = acc;
    }
}

__global__ void __launch_bounds__(NTHR, 4)
k_uber(const float* __restrict__ x, const int* __restrict__ ei,
       const int* __restrict__ batch,
       const float* __restrict__ W1, const float* __restrict__ b1,
       const float* __restrict__ W2, const float* __restrict__ b2,
       const float* __restrict__ W3, const float* __restrict__ b3,
       const float* __restrict__ Wl, const float* __restrict__ bl,
       float* __restrict__ out) {
    const int NT   = gridDim.x * blockDim.x;
    const int gt   = blockIdx.x * blockDim.x + threadIdx.x;
    const int lane = threadIdx.x & 31;
    const int wid  = gt >> 5;
    const int nw   = NT >> 5;
    __shared__ int sh[512];

    // ---- P0: init + dtype detection ----
    for (int i = gt; i < N_NODES; i += NT) d_deg[i] = 1;        // self-loop
    for (int i = gt; i < N_GRAPHS * HID; i += NT) d_gsum[i] = 0.f;
    for (int i = gt; i < N_GRAPHS; i += NT) d_gcnt[i] = 0;
    if (blockIdx.x == 0) {
        __shared__ int s_ei, s_b;
        if (threadIdx.x == 0) { s_ei = 1; s_b = 1; }
        __syncthreads();
        for (int k = 0; k < 8; k++) {
            int t = threadIdx.x * 8 + k;
            if (__ldg(ei + ((t * (2 * N_EDGES / 2048)) | 1)) != 0) s_ei = 0;
            if (__ldg(batch + ((t * (N_NODES / 2048)) | 1)) != 0) s_b = 0;
        }
        __syncthreads();
        if (threadIdx.x == 0) { d_ei64 = s_ei; d_b64 = s_b; }
    }
    gbar();
    const int ef = d_ei64;
    const int bf = d_b64;

    // ---- P1: degree histogram ----
    for (int e = gt; e < N_EDGES; e += NT)
        atomicAdd(&d_deg[ld_idx(ei, N_EDGES + e, ef)], 1);
    gbar();

    // ---- P2: dis = rsqrt(deg) + scan phase A ----
    for (int i = gt; i < N_NODES; i += NT)
        d_dis[i] = rsqrtf((float)d_deg[i]);
    if (blockIdx.x < NSC) {
        int i = blockIdx.x * NTHR + threadIdx.x;
        int c = (i < N_NODES) ? (d_deg[i] - 1) : 0;
        sh[threadIdx.x] = c;
        __syncthreads();
        #pragma unroll
        for (int off = 1; off < NTHR; off <<= 1) {
            int t = (threadIdx.x >= off) ? sh[threadIdx.x - off] : 0;
            __syncthreads();
            sh[threadIdx.x] += t;
            __syncthreads();
        }
        if (i < N_NODES) d_rowptr[i] = sh[threadIdx.x] - c;
        if (threadIdx.x == NTHR - 1) d_bsum[blockIdx.x] = sh[NTHR - 1];
    }
    gbar();

    // ---- P3: scan phase B ----
    if (blockIdx.x == 0) {
        for (int t = threadIdx.x; t < NSC; t += NTHR) sh[t] = d_bsum[t];
        __syncthreads();
        if (threadIdx.x == 0) {
            int run = 0;
            for (int b = 0; b < NSC; b++) { int t = sh[b]; sh[b] = run; run += t; }
        }
        __syncthreads();
        for (int t = threadIdx.x; t < NSC; t += NTHR) d_bsum[t] = sh[t];
    }
    gbar();

    // ---- P4: scan phase C ----
    for (int i = gt; i < N_NODES; i += NT) {
        int v = d_rowptr[i] + d_bsum[i / NTHR];
        d_rowptr[i] = v;
        d_cursor[i] = v;
    }
    gbar();

    // ---- P5: CSR fill ----
    for (int e = gt; e < N_EDGES; e += NT) {
        int s = ld_idx(ei, e, ef);
        int d = ld_idx(ei, N_EDGES + e, ef);
        d_csr_src[atomicAdd(&d_cursor[d], 1)] = s;
    }
    gbar();

    // ---- P6: fused xa-gather + layer-1 transform (warp per node) ----
    for (int node = wid; node < N_NODES; node += nw) {
        float dv = d_dis[node];
        float a = 0.f;
        if (lane < IN_F)
            a = dv * dv * __ldg(x + (size_t)node * IN_F + lane);
        int st = d_rowptr[node], cnt = d_deg[node] - 1;
        for (int j = 0; j < cnt; j++) {
            int s = __ldg(d_csr_src + st + j);
            float w = __ldg(&d_dis[s]) * dv;
            if (lane < IN_F)
                a += w * __ldg(x + (size_t)s * IN_F + lane);
        }
        float4 acc = __ldg((const float4*)b1 + lane);
        #pragma unroll
        for (int k = 0; k < IN_F; k++) {
            float v = __shfl_sync(0xffffffffu, a, k);
            float4 w = __ldg((const float4*)W1 + k * 32 + lane);
            acc.x += v * w.x; acc.y += v * w.y;
            acc.z += v * w.z; acc.w += v * w.w;
        }
        acc.x = fmaxf(acc.x, 0.f); acc.y = fmaxf(acc.y, 0.f);
        acc.z = fmaxf(acc.z, 0.f); acc.w = fmaxf(acc.w, 0.f);
        ((float4*)(d_h1 + (size_t)node * HID))[lane] = acc;
    }
    gbar();

    // ---- P7-P8: layer 2 ----
    xform128(W2, wid, nw, lane); gbar();
    gather128(b2, 1, wid, nw, lane); gbar();
    // ---- P9-P10: layer 3 (no relu) ----
    xform128(W3, wid, nw, lane); gbar();
    gather128(b3, 0, wid, nw, lane); gbar();

    // ---- P11: segmented mean-pool (batch sorted => few flushes) ----
    {
        int per = (N_NODES + nw - 1) / nw;
        int n0 = wid * per;
        int n1 = (n0 + per < N_NODES) ? n0 + per : N_NODES;
        if (n0 < n1) {
            float4 acc = make_float4(0.f, 0.f, 0.f, 0.f);
            int cnt = 0;
            int curg = ld_idx(batch, n0, bf);
            for (int n = n0; n < n1; n++) {
                int g = ld_idx(batch, n, bf);
                if (g != curg) {
                    float* base = d_gsum + curg * HID + lane * 4;
                    atomicAdd(base + 0, acc.x); atomicAdd(base + 1, acc.y);
                    atomicAdd(base + 2, acc.z); atomicAdd(base + 3, acc.w);
                    if (lane == 0) atomicAdd(&d_gcnt[curg], cnt);
                    acc = make_float4(0.f, 0.f, 0.f, 0.f);
                    cnt = 0;
                    curg = g;
                }
                float4 v = ((const float4*)(d_h1 + (size_t)n * HID))[lane];
                acc.x += v.x; acc.y += v.y; acc.z += v.z; acc.w += v.w;
                cnt++;
            }
            float* base = d_gsum + curg * HID + lane * 4;
            atomicAdd(base + 0, acc.x); atomicAdd(base + 1, acc.y);
            atomicAdd(base + 2, acc.z); atomicAdd(base + 3, acc.w);
            if (lane == 0) atomicAdd(&d_gcnt[curg], cnt);
        }
    }
    gbar();

    // ---- P12: head ----
    for (int i = gt; i < N_GRAPHS * OUT_F; i += NT) {
        int g = i / OUT_F, c = i - g * OUT_F;
        float inv = 1.f / (float)max(d_gcnt[g], 1);
        float acc = __ldg(bl + c);
        #pragma unroll 8
        for (int k = 0; k < HID; k++)
            acc += (d_gsum[g * HID + k] * inv) * __ldg(Wl + k * OUT_F + c);
        out[i] = acc;
    }
}

// ---------------- launch ---------------------------------------------------------
extern "C" void kernel_launch(void* const* d_in, const int* in_sizes, int n_in,
                              void* d_out, int out_size) {
    const float *x = 0, *W1 = 0, *W2 = 0, *W3 = 0, *Wl = 0, *bl = 0;
    const float *bias[3] = {0, 0, 0};
    const int *ei = 0, *batch = 0;
    int nbias = 0, nW = 0;
    for (int i = 0; i < n_in; i++) {
        int sz = in_sizes[i];
        const void* p = d_in[i];
        switch (sz) {
            case N_NODES * IN_F:   x     = (const float*)p;  break;
            case 2 * N_EDGES:      ei    = (const int*)p;    break;
            case N_NODES:          batch = (const int*)p;    break;
            case IN_F * HID:       W1    = (const float*)p;  break;
            case HID * HID:        if (nW == 0) W2 = (const float*)p; else W3 = (const float*)p; nW++; break;
            case HID:              if (nbias < 3) bias[nbias++] = (const float*)p; break;
            case HID * OUT_F:      Wl    = (const float*)p;  break;
            case OUT_F:            bl    = (const float*)p;  break;
            default: break;
        }
    }

    int sm = 148, mb = 1;
    cudaDeviceGetAttribute(&sm, cudaDevAttrMultiProcessorCount, 0);
    cudaOccupancyMaxActiveBlocksPerMultiprocessor(&mb, k_uber, NTHR, 0);
    if (mb < 1) mb = 1;
    if (mb > 4) mb = 4;
    int grid = sm * mb;

    k_uber<<<grid, NTHR>>>(x, ei, batch,
                           W1, bias[0], W2, bias[1], W3, bias[2],
                           Wl, bl, (float*)d_out);
}

// round 17
// speedup vs baseline: 1.4843x; 1.3095x over previous
#include <cuda_runtime.h>

#define N_NODES  100000
#define N_EDGES  1600000
#define HID      128
#define IN_F     10
#define OUT_F    101
#define N_GRAPHS 64
#define NTHR     256
#define NSC      ((N_NODES + NTHR - 1) / NTHR)   // 391 scan blocks

// ---------------- device state (single-launch lifetime) ------------------------
__device__ __align__(16) float d_h0[(size_t)N_NODES * HID];
__device__ __align__(16) float d_h1[(size_t)N_NODES * HID];
__device__ int   d_deg[N_NODES];
__device__ float d_dis[N_NODES];
__device__ int   d_rowptr[N_NODES];
__device__ int   d_cursor[N_NODES];
__device__ int   d_bsum[NSC];
__device__ int   d_csr_src[N_EDGES];
__device__ float d_gsum[N_GRAPHS * HID];
__device__ int   d_gcnt[N_GRAPHS];
__device__ __align__(16) float d_wfuse[HID * OUT_F];   // W3 @ Wl
__device__ float d_bfuse[OUT_F];                       // b3 @ Wl + bl
__device__ int   d_ei64, d_b64;
__device__ int          g_arrive;     // arrival ticket (monotonic)
__device__ volatile int g_release;    // generation release word (monotonic)

__device__ __forceinline__ int ld_idx(const int* __restrict__ p, int i, int is64) {
    return is64 ? __ldg(p + 2 * (size_t)i) : __ldg(p + i);
}

// packed fp32x2 FMA (full-rate fp32 on sm_103a; plain FFMA is half-rate)
#define FFMA2(acc, a, b) \
    asm("fma.rn.f32x2 %0, %1, %2, %0;" : "+l"(acc) : "l"(a), "l"(b))
#define PACKVV(out, v) \
    asm("mov.b64 %0, {%1, %1};" : "=l"(out) : "r"(__float_as_uint(v)))

// Grid barrier v2 (R16-validated): atomic ARRIVE only; waiters poll plain word.
__device__ __forceinline__ void gbar() {
    __syncthreads();
    if (threadIdx.x == 0) {
        __threadfence();
        int g   = gridDim.x;
        int t   = atomicAdd(&g_arrive, 1);
        int gen = t / g;
        if (t % g == g - 1) {
            g_release = gen + 1;
        } else {
            while (g_release <= gen) __nanosleep(64);
        }
        __threadfence();
    }
    __syncthreads();
}

__global__ void __launch_bounds__(NTHR, 4)
k_uber(const float* __restrict__ x, const int* __restrict__ ei,
       const int* __restrict__ batch,
       const float* __restrict__ W1, const float* __restrict__ b1,
       const float* __restrict__ W2, const float* __restrict__ b2,
       const float* __restrict__ W3, const float* __restrict__ b3,
       const float* __restrict__ Wl, const float* __restrict__ bl,
       float* __restrict__ out) {
    const int NT   = gridDim.x * blockDim.x;
    const int gt   = blockIdx.x * blockDim.x + threadIdx.x;
    const int lane = threadIdx.x & 31;
    const int wid  = gt >> 5;
    const int nw   = NT >> 5;
    __shared__ int sh[512];

    // ---- P0: init + dtype detection + head-weight fusion ----
    for (int i = gt; i < N_NODES; i += NT) d_deg[i] = 1;        // self-loop
    for (int i = gt; i < N_GRAPHS * HID; i += NT) d_gsum[i] = 0.f;
    for (int i = gt; i < N_GRAPHS; i += NT) d_gcnt[i] = 0;
    // Wf = W3 @ Wl  (128x101), bf = b3 @ Wl + bl  (inputs only; no deps)
    for (int i = gt; i < HID * OUT_F; i += NT) {
        int k = i / OUT_F, c = i - k * OUT_F;
        float acc = 0.f;
        #pragma unroll 8
        for (int j = 0; j < HID; j++)
            acc += __ldg(W3 + k * HID + j) * __ldg(Wl + j * OUT_F + c);
        d_wfuse[i] = acc;
    }
    for (int i = gt; i < OUT_F; i += NT) {
        float acc = __ldg(bl + i);
        #pragma unroll 8
        for (int j = 0; j < HID; j++)
            acc += __ldg(b3 + j) * __ldg(Wl + j * OUT_F + i);
        d_bfuse[i] = acc;
    }
    if (blockIdx.x == 0) {
        __shared__ int s_ei, s_b;
        if (threadIdx.x == 0) { s_ei = 1; s_b = 1; }
        __syncthreads();
        for (int k = 0; k < 8; k++) {
            int t = threadIdx.x * 8 + k;
            if (__ldg(ei + ((t * (2 * N_EDGES / 2048)) | 1)) != 0) s_ei = 0;
            if (__ldg(batch + ((t * (N_NODES / 2048)) | 1)) != 0) s_b = 0;
        }
        __syncthreads();
        if (threadIdx.x == 0) { d_ei64 = s_ei; d_b64 = s_b; }
    }
    gbar();
    const int ef = d_ei64;
    const int bf = d_b64;

    // ---- P1: degree histogram ----
    for (int e = gt; e < N_EDGES; e += NT)
        atomicAdd(&d_deg[ld_idx(ei, N_EDGES + e, ef)], 1);
    gbar();

    // ---- P2: dis = rsqrt(deg) + scan phase A ----
    for (int i = gt; i < N_NODES; i += NT)
        d_dis[i] = rsqrtf((float)d_deg[i]);
    if (blockIdx.x < NSC) {
        int i = blockIdx.x * NTHR + threadIdx.x;
        int c = (i < N_NODES) ? (d_deg[i] - 1) : 0;
        sh[threadIdx.x] = c;
        __syncthreads();
        #pragma unroll
        for (int off = 1; off < NTHR; off <<= 1) {
            int t = (threadIdx.x >= off) ? sh[threadIdx.x - off] : 0;
            __syncthreads();
            sh[threadIdx.x] += t;
            __syncthreads();
        }
        if (i < N_NODES) d_rowptr[i] = sh[threadIdx.x] - c;
        if (threadIdx.x == NTHR - 1) d_bsum[blockIdx.x] = sh[NTHR - 1];
    }
    gbar();

    // ---- P3: scan phase B ----
    if (blockIdx.x == 0) {
        for (int t = threadIdx.x; t < NSC; t += NTHR) sh[t] = d_bsum[t];
        __syncthreads();
        if (threadIdx.x == 0) {
            int run = 0;
            for (int b = 0; b < NSC; b++) { int t = sh[b]; sh[b] = run; run += t; }
        }
        __syncthreads();
        for (int t = threadIdx.x; t < NSC; t += NTHR) d_bsum[t] = sh[t];
    }
    gbar();

    // ---- P4: scan phase C ----
    for (int i = gt; i < N_NODES; i += NT) {
        int v = d_rowptr[i] + d_bsum[i / NTHR];
        d_rowptr[i] = v;
        d_cursor[i] = v;
    }
    gbar();

    // ---- P5: CSR fill ----
    for (int e = gt; e < N_EDGES; e += NT) {
        int s = ld_idx(ei, e, ef);
        int d = ld_idx(ei, N_EDGES + e, ef);
        d_csr_src[atomicAdd(&d_cursor[d], 1)] = s;
    }
    gbar();

    // ---- P6: fused xa-gather + layer-1 transform (warp per node) ----
    for (int node = wid; node < N_NODES; node += nw) {
        float dv = d_dis[node];
        float a = 0.f;
        if (lane < IN_F)
            a = dv * dv * __ldg(x + (size_t)node * IN_F + lane);
        int st = d_rowptr[node], cnt = d_deg[node] - 1;
        for (int j = 0; j < cnt; j++) {
            int s = __ldg(d_csr_src + st + j);
            float w = __ldg(&d_dis[s]) * dv;
            if (lane < IN_F)
                a += w * __ldg(x + (size_t)s * IN_F + lane);
        }
        float4 acc = __ldg((const float4*)b1 + lane);
        #pragma unroll
        for (int k = 0; k < IN_F; k++) {
            float v = __shfl_sync(0xffffffffu, a, k);
            float4 w = __ldg((const float4*)W1 + k * 32 + lane);
            acc.x += v * w.x; acc.y += v * w.y;
            acc.z += v * w.z; acc.w += v * w.w;
        }
        acc.x = fmaxf(acc.x, 0.f); acc.y = fmaxf(acc.y, 0.f);
        acc.z = fmaxf(acc.z, 0.f); acc.w = fmaxf(acc.w, 0.f);
        ((float4*)(d_h1 + (size_t)node * HID))[lane] = acc;
    }
    gbar();

    // ---- P7: layer-2 transform: d_h0 = d_h1 @ W2 (f32x2 packed, 4 rows/warp) --
    for (int q = wid; q < N_NODES / 4; q += nw) {
        const float* r = d_h1 + (size_t)(4 * q) * HID;
        unsigned long long a01[4] = {0ull, 0ull, 0ull, 0ull};
        unsigned long long a23[4] = {0ull, 0ull, 0ull, 0ull};
        #pragma unroll 2
        for (int k4 = 0; k4 < HID; k4 += 4) {
            float4 xr[4];
            #pragma unroll
            for (int t = 0; t < 4; t++)
                xr[t] = *(const float4*)(r + t * HID + k4);
            #pragma unroll
            for (int kk = 0; kk < 4; kk++) {
                double2 wp = __ldg((const double2*)(W2 + (size_t)(k4 + kk) * HID) + lane);
                unsigned long long w01 = (unsigned long long)__double_as_longlong(wp.x);
                unsigned long long w23 = (unsigned long long)__double_as_longlong(wp.y);
                #pragma unroll
                for (int t = 0; t < 4; t++) {
                    float v = (kk == 0) ? xr[t].x : (kk == 1) ? xr[t].y
                             : (kk == 2) ? xr[t].z : xr[t].w;
                    unsigned long long vv;
                    PACKVV(vv, v);
                    FFMA2(a01[t], w01, vv);
                    FFMA2(a23[t], w23, vv);
                }
            }
        }
        #pragma unroll
        for (int t = 0; t < 4; t++) {
            double2 st;
            st.x = __longlong_as_double((long long)a01[t]);
            st.y = __longlong_as_double((long long)a23[t]);
            ((double2*)(d_h0 + (size_t)(4 * q + t) * HID))[lane] = st;
        }
    }
    gbar();

    // ---- P8: layer-2 gather: d_h1 = relu(A*d_h0 + b2) ----
    for (int node = wid; node < N_NODES; node += nw) {
        float dv = d_dis[node];
        float4 h = ((const float4*)(d_h0 + (size_t)node * HID))[lane];
        float sw = dv * dv;
        float4 acc;
        acc.x = sw * h.x; acc.y = sw * h.y; acc.z = sw * h.z; acc.w = sw * h.w;
        int st = d_rowptr[node];
        int cnt = d_deg[node] - 1;
        int sn = (cnt > 0) ? __ldg(d_csr_src + st) : 0;
        for (int j = 0; j < cnt; j++) {
            int s = sn;
            if (j + 1 < cnt) sn = __ldg(d_csr_src + st + j + 1);
            float w = __ldg(&d_dis[s]) * dv;
            float4 v = ((const float4*)(d_h0 + (size_t)s * HID))[lane];
            acc.x += w * v.x; acc.y += w * v.y;
            acc.z += w * v.z; acc.w += w * v.w;
        }
        float4 b = __ldg((const float4*)b2 + lane);
        acc.x = fmaxf(acc.x + b.x, 0.f); acc.y = fmaxf(acc.y + b.y, 0.f);
        acc.z = fmaxf(acc.z + b.z, 0.f); acc.w = fmaxf(acc.w + b.w, 0.f);
        ((float4*)(d_h1 + (size_t)node * HID))[lane] = acc;
    }
    gbar();

    // ---- P9: FUSED layer-3 gather + mean-pool ----
    // u[n] = (A*h2)[n]; pooled@W3@Wl == pooled_u @ Wfuse (pool linear, no relu).
    {
        int per = (N_NODES + nw - 1) / nw;
        int n0 = wid * per;
        int n1 = (n0 + per < N_NODES) ? n0 + per : N_NODES;
        if (n0 < n1) {
            float4 acc = make_float4(0.f, 0.f, 0.f, 0.f);
            int cnt = 0;
            int curg = ld_idx(batch, n0, bf);
            for (int n = n0; n < n1; n++) {
                int g = ld_idx(batch, n, bf);
                if (g != curg) {
                    float* base = d_gsum + curg * HID + lane * 4;
                    atomicAdd(base + 0, acc.x); atomicAdd(base + 1, acc.y);
                    atomicAdd(base + 2, acc.z); atomicAdd(base + 3, acc.w);
                    if (lane == 0) atomicAdd(&d_gcnt[curg], cnt);
                    acc = make_float4(0.f, 0.f, 0.f, 0.f);
                    cnt = 0;
                    curg = g;
                }
                float dv = d_dis[n];
                float4 h = ((const float4*)(d_h1 + (size_t)n * HID))[lane];
                float sw = dv * dv;
                float4 u;
                u.x = sw * h.x; u.y = sw * h.y; u.z = sw * h.z; u.w = sw * h.w;
                int st = d_rowptr[n];
                int ec = d_deg[n] - 1;
                int sn2 = (ec > 0) ? __ldg(d_csr_src + st) : 0;
                for (int j = 0; j < ec; j++) {
                    int s = sn2;
                    if (j + 1 < ec) sn2 = __ldg(d_csr_src + st + j + 1);
                    float w = __ldg(&d_dis[s]) * dv;
                    float4 v = ((const float4*)(d_h1 + (size_t)s * HID))[lane];
                    u.x += w * v.x; u.y += w * v.y;
                    u.z += w * v.z; u.w += w * v.w;
                }
                acc.x += u.x; acc.y += u.y; acc.z += u.z; acc.w += u.w;
                cnt++;
            }
            float* base = d_gsum + curg * HID + lane * 4;
            atomicAdd(base + 0, acc.x); atomicAdd(base + 1, acc.y);
            atomicAdd(base + 2, acc.z); atomicAdd(base + 3, acc.w);
            if (lane == 0) atomicAdd(&d_gcnt[curg], cnt);
        }
    }
    gbar();

    // ---- P10: head: out[g] = (gsum[g]/cnt) @ Wfuse + bfuse ----
    for (int i = gt; i < N_GRAPHS * OUT_F; i += NT) {
        int g = i / OUT_F, c = i - g * OUT_F;
        float inv = 1.f / (float)max(d_gcnt[g], 1);
        float acc = d_bfuse[c];
        #pragma unroll 8
        for (int k = 0; k < HID; k++)
            acc += (d_gsum[g * HID + k] * inv) * d_wfuse[k * OUT_F + c];
        out[i] = acc;
    }
}

// ---------------- launch ---------------------------------------------------------
extern "C" void kernel_launch(void* const* d_in, const int* in_sizes, int n_in,
                              void* d_out, int out_size) {
    const float *x = 0, *W1 = 0, *W2 = 0, *W3 = 0, *Wl = 0, *bl = 0;
    const float *bias[3] = {0, 0, 0};
    const int *ei = 0, *batch = 0;
    int nbias = 0, nW = 0;
    for (int i = 0; i < n_in; i++) {
        int sz = in_sizes[i];
        const void* p = d_in[i];
        switch (sz) {
            case N_NODES * IN_F:   x     = (const float*)p;  break;
            case 2 * N_EDGES:      ei    = (const int*)p;    break;
            case N_NODES:          batch = (const int*)p;    break;
            case IN_F * HID:       W1    = (const float*)p;  break;
            case HID * HID:        if (nW == 0) W2 = (const float*)p; else W3 = (const float*)p; nW++; break;
            case HID:              if (nbias < 3) bias[nbias++] = (const float*)p; break;
            case HID * OUT_F:      Wl    = (const float*)p;  break;
            case OUT_F:            bl    = (const float*)p;  break;
            default: break;
        }
    }

    int sm = 148, mb = 1;
    cudaDeviceGetAttribute(&sm, cudaDevAttrMultiProcessorCount, 0);
    cudaOccupancyMaxActiveBlocksPerMultiprocessor(&mb, k_uber, NTHR, 0);
    if (mb < 1) mb = 1;
    if (mb > 4) mb = 4;
    int grid = sm * mb;

    k_uber<<<grid, NTHR>>>(x, ei, batch,
                           W1, bias[0], W2, bias[1], W3, bias[2],
                           Wl, bl, (float*)d_out);
}